// round 8
// baseline (speedup 1.0000x reference)
#include <cuda_runtime.h>
#include <cstdint>

#define TWO_N 8192
#define NHALF 4096
#define DDIM  256
#define BM 128
#define NBLK 2080            // 64*65/2 upper-triangle 128x128 blocks
#define NCTA 148
#define NTHR 256             // 8 warps: 4(M) x 2(N), warp tile 32x64
#define CHUNK_BYTES 16384    // one [128 rows][128B] swizzled k-chunk
#define TILE_BYTES  32768    // 128 x 256 int8

__device__ char  g_znq[TWO_N * DDIM];       // quantized rows (scale 256)
__device__ float g_pr[(size_t)NBLK * 128];  // per-block row partial sums
__device__ float g_pc[(size_t)NBLK * 128];  // per-block col partial sums
__device__ float g_bs[64];                  // per-rowblock loss partial
__device__ int   g_cnt;                     // last-block counter

#define L2E2 2.8853900817779268f            /* 2/ln2 */
#define CONV (L2E2 / 65536.0f)              /* s32 -> 2^(sim/ln2) exponent */

// ---------------------------------------------------------------- helpers --
__device__ __forceinline__ uint32_t smem_u32(const void* p) {
    uint32_t a;
    asm("{ .reg .u64 t; cvta.to.shared.u64 t, %1; cvt.u32.u64 %0, t; }"
        : "=r"(a) : "l"(p));
    return a;
}
__device__ __forceinline__ float ex2f(float x) {
    float y; asm("ex2.approx.f32 %0, %1;" : "=f"(y) : "f"(x)); return y;
}
#define CP_ASYNC16(sm, gp) \
    asm volatile("cp.async.cg.shared.global [%0], [%1], 16;" \
                 :: "r"(sm), "l"(gp) : "memory")
#define CP_COMMIT()  asm volatile("cp.async.commit_group;" ::: "memory")
#define CP_WAIT(n)   asm volatile("cp.async.wait_group %0;" :: "n"(n) : "memory")

__device__ __forceinline__ void ldsm_x4(uint32_t* r, uint32_t addr) {
    asm volatile("ldmatrix.sync.aligned.m8n8.x4.shared.b16 {%0,%1,%2,%3}, [%4];"
                 : "=r"(r[0]), "=r"(r[1]), "=r"(r[2]), "=r"(r[3]) : "r"(addr));
}
// int8 IMMA: 16x8x32, s32 accumulate
__device__ __forceinline__ void mma16832i(int* c, const uint32_t* a,
                                          uint32_t b0, uint32_t b1) {
    asm volatile(
        "mma.sync.aligned.m16n8k32.row.col.s32.s8.s8.s32 "
        "{%0,%1,%2,%3}, {%4,%5,%6,%7}, {%8,%9}, {%0,%1,%2,%3};"
        : "+r"(c[0]), "+r"(c[1]), "+r"(c[2]), "+r"(c[3])
        : "r"(a[0]), "r"(a[1]), "r"(a[2]), "r"(a[3]), "r"(b0), "r"(b1));
}
__device__ __forceinline__ int dp4a(int a, int b, int c) {
    int d; asm("dp4a.s32.s32 %0, %1, %2, %3;" : "=r"(d) : "r"(a), "r"(b), "r"(c));
    return d;
}

// upper-triangle block id in paired-strip order
__device__ __forceinline__ int bidx(int I, int J) {   // I <= J
    return (I < 32) ? (64 * I + J) : (65 * (63 - I) + I + 1 + (J - I));
}
__device__ __forceinline__ void bdecode(int g, int& I, int& J) {
    int p = g / 65, r = g - p * 65;
    if (r < 64 - p) { I = p;      J = p + r; }
    else            { I = 63 - p; J = I + (r - (64 - p)); }
}

// ---------------------------------------------------------------------------
// Kernel 1: L2-normalize rows -> int8 (scale 256). 2 rows per warp.
// ---------------------------------------------------------------------------
__global__ void norm_kernel(const float* __restrict__ z1,
                            const float* __restrict__ z2) {
    int wid = threadIdx.x >> 5, lane = threadIdx.x & 31;
#pragma unroll
    for (int rr = 0; rr < 2; rr++) {
        int row = (blockIdx.x * 8 + wid) * 2 + rr;
        const float4* src = reinterpret_cast<const float4*>(
            (row < NHALF) ? (z1 + (size_t)row * DDIM)
                          : (z2 + (size_t)(row - NHALF) * DDIM));
        float4 v0 = src[lane];
        float4 v1 = src[lane + 32];
        float ss = v0.x * v0.x + v0.y * v0.y + v0.z * v0.z + v0.w * v0.w
                 + v1.x * v1.x + v1.y * v1.y + v1.z * v1.z + v1.w * v1.w;
#pragma unroll
        for (int o = 16; o; o >>= 1) ss += __shfl_xor_sync(0xffffffffu, ss, o);
        float inv = 256.0f / fmaxf(sqrtf(ss), 1e-8f);
        int q0 = __float2int_rn(v0.x * inv), q1 = __float2int_rn(v0.y * inv);
        int q2 = __float2int_rn(v0.z * inv), q3 = __float2int_rn(v0.w * inv);
        int q4 = __float2int_rn(v1.x * inv), q5 = __float2int_rn(v1.y * inv);
        int q6 = __float2int_rn(v1.z * inv), q7 = __float2int_rn(v1.w * inv);
        uint32_t pa = (q0 & 0xff) | ((q1 & 0xff) << 8) |
                      ((q2 & 0xff) << 16) | ((uint32_t)q3 << 24);
        uint32_t pb = (q4 & 0xff) | ((q5 & 0xff) << 8) |
                      ((q6 & 0xff) << 16) | ((uint32_t)q7 << 24);
        uint2* dst = reinterpret_cast<uint2*>(g_znq + (size_t)row * DDIM);
        // lane covers bytes [lane*4 .. +3] and [128 + lane*4 .. +3]
        reinterpret_cast<uint32_t*>(dst)[lane]      = pa;
        reinterpret_cast<uint32_t*>(dst)[lane + 32] = pb;
    }
}

// ---------------------------------------------------------------------------
// tile loader: 128 rows x 256 int8 -> swizzled k-chunks via cp.async
// ---------------------------------------------------------------------------
__device__ __forceinline__ void load_tile(uint32_t sdst, int rowblk, int tid) {
    const char* gsrc = g_znq + (size_t)rowblk * BM * DDIM;
#pragma unroll
    for (int i = 0; i < 8; i++) {
        int unit = i * NTHR + tid;           // 2048 16B units; 16 per row
        int row = unit >> 4, uu = unit & 15;
        uint32_t off = (uint32_t)(row * 128 + (uu & 7) * 16);
        off ^= (off >> 3) & 0x70;
        CP_ASYNC16(sdst + (uu >> 3) * CHUNK_BYTES + off, gsrc + unit * 16);
    }
}

// ---------------------------------------------------------------------------
// Kernel 2: symmetric int8 IMMA GEMM over upper-triangle blocks,
// deferred exp epilogue. 148 persistent CTAs, paired-strip order.
// ---------------------------------------------------------------------------
__global__ void __launch_bounds__(NTHR, 1) sim_kernel() {
    extern __shared__ char smem_raw[];
    char* sbase = (char*)(((uintptr_t)smem_raw + 1023) & ~(uintptr_t)1023);
    uint32_t sAu = smem_u32(sbase);              // A: 32 KB (single)
    uint32_t sBu = sAu + TILE_BYTES;             // B: 2 x 32 KB

    __shared__ float s_rs[2][BM];                // n-half rowsum partials
    __shared__ float s_cs[8][64];                // [mwarp*2+nhalf][col]

    int tid = threadIdx.x;
    int wid = tid >> 5, lane = tid & 31;
    int cta = blockIdx.x;
    int start = cta * 14 + (cta < 8 ? cta : 8);
    int cnt = 14 + (cta < 8 ? 1 : 0);

    int m_base = (wid >> 1) * 32;
    int n_base = (wid & 1) * 64;
    int mwarp = wid >> 1, nhalf = wid & 1;

    // ---- per-lane ldmatrix address pieces (16B units; k-step = 32 int8) ----
    int rA0 = m_base + (lane & 15);
    int rA1 = rA0 + 16;
    uint32_t kaddA = ((lane >> 4) & 1) * 16;     // k lo/hi 16B unit
    uint32_t rowA0 = (uint32_t)rA0 * 128, xA0 = (uint32_t)(rA0 & 7) << 4;
    uint32_t rowA1 = (uint32_t)rA1 * 128, xA1 = (uint32_t)(rA1 & 7) << 4;
    int rBb = n_base + (lane & 7) + ((lane & 16) >> 1);
    uint32_t kaddB = ((lane >> 3) & 1) * 16;
    uint32_t rowB[4], xB[4];
#pragma unroll
    for (int gI = 0; gI < 4; gI++) {
        int r = rBb + gI * 16;
        rowB[gI] = (uint32_t)r * 128;
        xB[gI] = (uint32_t)(r & 7) << 4;
    }
    int lrow[4];
#pragma unroll
    for (int s = 0; s < 4; s++)
        lrow[s] = m_base + (s >> 1) * 16 + (lane >> 2) + (s & 1) * 8;

    int accA[2][8][4], accB[2][8][4];            // s32 accumulators
    float rs[4] = {0.f, 0.f, 0.f, 0.f};
    float cs[8][2];
#pragma unroll
    for (int j = 0; j < 8; j++) { cs[j][0] = 0.f; cs[j][1] = 0.f; }
    int curI;

    auto flush_old = [&](int oI, int oJ, int oblk) {
#pragma unroll
        for (int s2 = 0; s2 < 4; s2++) {
            float v = rs[s2];
            v += __shfl_xor_sync(0xffffffffu, v, 1);
            v += __shfl_xor_sync(0xffffffffu, v, 2);
            if ((lane & 3) == 0) s_rs[nhalf][lrow[s2]] = v;
        }
        if (oI != oJ) {
#pragma unroll
            for (int j = 0; j < 8; j++)
#pragma unroll
                for (int cb = 0; cb < 2; cb++) {
                    float v = cs[j][cb];
                    v += __shfl_xor_sync(0xffffffffu, v, 4);
                    v += __shfl_xor_sync(0xffffffffu, v, 8);
                    v += __shfl_xor_sync(0xffffffffu, v, 16);
                    if (lane < 4)
                        s_cs[mwarp * 2 + nhalf][j * 8 + lane * 2 + cb] = v;
                }
        }
        __syncthreads();
        if (tid < BM) {
            size_t boff = (size_t)oblk * 128 + tid;
            g_pr[boff] = s_rs[0][tid] + s_rs[1][tid];
            if (oI != oJ) {
                int nh = tid >> 6, cc = tid & 63;
                g_pc[boff] = s_cs[nh][cc] + s_cs[2 + nh][cc] +
                             s_cs[4 + nh][cc] + s_cs[6 + nh][cc];
            }
        }
#pragma unroll
        for (int s2 = 0; s2 < 4; s2++) rs[s2] = 0.f;
#pragma unroll
        for (int j = 0; j < 8; j++) { cs[j][0] = 0.f; cs[j][1] = 0.f; }
    };

    auto run_block = [&](int (&acc)[2][8][4], int (&aold)[2][8][4],
                         int n, int oI, int oJ, bool do_old) {
        if (n + 1 < cnt) {
            int In, Jn; bdecode(start + n + 1, In, Jn);
            load_tile(sBu + ((n + 1) & 1) * TILE_BYTES, Jn, tid);
            CP_COMMIT();
            CP_WAIT(1);
        } else {
            CP_WAIT(0);
        }
        __syncthreads();

#pragma unroll
        for (int i = 0; i < 2; i++)
#pragma unroll
            for (int j = 0; j < 8; j++)
#pragma unroll
                for (int q = 0; q < 4; q++) acc[i][j][q] = 0;

        uint32_t bbase = sBu + (n & 1) * TILE_BYTES;

#pragma unroll
        for (int s = 0; s < 8; s++) {            // k = s*32 int8
            uint32_t coff = (uint32_t)(s >> 2) * CHUNK_BYTES;
            uint32_t kbA = (uint32_t)(s & 3) * 32 + kaddA;
            uint32_t kbB = (uint32_t)(s & 3) * 32 + kaddB;
            uint32_t a0[4], a1[4], b[4][4];
            ldsm_x4(a0, sAu + coff + rowA0 + (kbA ^ xA0));
            ldsm_x4(a1, sAu + coff + rowA1 + (kbA ^ xA1));
#pragma unroll
            for (int gI = 0; gI < 4; gI++)
                ldsm_x4(b[gI], bbase + coff + rowB[gI] + (kbB ^ xB[gI]));

            // deferred epilogue: column-group s of old block (8 values)
            if (do_old) {
                const int jj = s;
#pragma unroll
                for (int ii = 0; ii < 2; ii++)
#pragma unroll
                    for (int q = 0; q < 4; q++) {
                        float d = (float)aold[ii][jj][q];
                        float e = ex2f(d * CONV);
                        rs[ii * 2 + (q >> 1)] += e;
                        cs[jj][q & 1] += e;
                    }
            }

#pragma unroll
            for (int j = 0; j < 8; j++) {
                uint32_t b0 = b[j >> 1][(j & 1) * 2];
                uint32_t b1 = b[j >> 1][(j & 1) * 2 + 1];
                mma16832i(acc[0][j], a0, b0, b1);
                mma16832i(acc[1][j], a1, b0, b1);
            }
        }
        __syncthreads();   // sA / sB[n&1] no longer read

        if (n + 1 < cnt) {
            int In, Jn; bdecode(start + n + 1, In, Jn);
            if (In != curI) { load_tile(sAu, In, tid); CP_COMMIT(); curI = In; }
        }
        if (do_old) flush_old(oI, oJ, start + n - 1);
    };

    // ---- prologue ----
    int I0, J0; bdecode(start, I0, J0);
    load_tile(sAu, I0, tid); CP_COMMIT();
    load_tile(sBu, J0, tid); CP_COMMIT();
    curI = I0;

    bool useA = true;
    int pI = 0, pJ = 0;
#pragma unroll 1
    for (int n = 0; n < cnt; n++) {
        int I, J; bdecode(start + n, I, J);
        if (useA) run_block(accA, accB, n, pI, pJ, n > 0);
        else      run_block(accB, accA, n, pI, pJ, n > 0);
        useA = !useA; pI = I; pJ = J;
    }

    // ---- final (non-interleaved) epilogue for the last block ----
    {
        __syncthreads();
#pragma unroll
        for (int ii = 0; ii < 2; ii++)
#pragma unroll
            for (int jj = 0; jj < 8; jj++)
#pragma unroll
                for (int q = 0; q < 4; q++) {
                    float d = (float)(useA ? accB[ii][jj][q] : accA[ii][jj][q]);
                    float e = ex2f(d * CONV);
                    rs[ii * 2 + (q >> 1)] += e;
                    cs[jj][q & 1] += e;
                }
        flush_old(pI, pJ, start + cnt - 1);
    }
}

// ---------------------------------------------------------------------------
// Kernel 3: per-row combine; exact integer self/pos dots via dp4a; mean.
// ---------------------------------------------------------------------------
__global__ void reduce_kernel(float* __restrict__ out) {
    int R = blockIdx.x, q = threadIdx.x;     // 64 blocks x 128 threads
    int r = R * 128 + q;
    int p = r ^ NHALF;                       // positive-pair row

    // exact integer self & pair dots (bit-identical to IMMA results)
    const int* va = reinterpret_cast<const int*>(g_znq + (size_t)r * DDIM);
    const int* vb = reinterpret_cast<const int*>(g_znq + (size_t)p * DDIM);
    int ddi = 0, pdi = 0;
#pragma unroll 16
    for (int i = 0; i < DDIM / 4; i++) {
        int wa = va[i], wb = vb[i];
        ddi = dp4a(wa, wa, ddi);
        pdi = dp4a(wa, wb, pdi);
    }

    float tot = 0.f;
#pragma unroll 4
    for (int J = R; J < 64; J++) tot += g_pr[(size_t)bidx(R, J) * 128 + q];
#pragma unroll 4
    for (int I = 0; I < R; I++)  tot += g_pc[(size_t)bidx(I, R) * 128 + q];
    tot -= ex2f((float)ddi * CONV);          // remove self term (bit-exact)
    float lv = logf(tot) - (float)pdi * (2.0f / 65536.0f);

    int lane = q & 31;
#pragma unroll
    for (int o = 16; o; o >>= 1) lv += __shfl_xor_sync(0xffffffffu, lv, o);
    __shared__ float w[4];
    __shared__ int slast;
    __shared__ float aa[2];
    if (lane == 0) w[q >> 5] = lv;
    __syncthreads();
    if (q == 0) {
        g_bs[R] = w[0] + w[1] + w[2] + w[3];
        __threadfence();
        slast = (atomicAdd(&g_cnt, 1) == 63);
    }
    __syncthreads();
    if (slast) {
        __threadfence();
        if (q < 64) {
            float v = g_bs[q];
#pragma unroll
            for (int o = 16; o; o >>= 1) v += __shfl_xor_sync(0xffffffffu, v, o);
            if ((q & 31) == 0) aa[q >> 5] = v;
        }
        __syncthreads();
        if (q == 0) {
            out[0] = (aa[0] + aa[1]) / (float)TWO_N;
            g_cnt = 0;                       // reset for graph replay
        }
    }
}

// ---------------------------------------------------------------------------
extern "C" void kernel_launch(void* const* d_in, const int* in_sizes, int n_in,
                              void* d_out, int out_size) {
    const float* z1 = (const float*)d_in[0];
    const float* z2 = (const float*)d_in[1];
    float* out = (float*)d_out;

    norm_kernel<<<TWO_N / 16, 256>>>(z1, z2);

    size_t smem = 3 * TILE_BYTES + 1024;   // 99,328 B
    cudaFuncSetAttribute(sim_kernel, cudaFuncAttributeMaxDynamicSharedMemorySize,
                         (int)smem);
    sim_kernel<<<NCTA, NTHR, smem>>>();

    reduce_kernel<<<64, 128>>>(out);
}

// round 9
// speedup vs baseline: 2.2058x; 2.2058x over previous
#include <cuda_runtime.h>
#include <cuda_bf16.h>
#include <cstdint>

#define TWO_N 8192
#define NHALF 4096
#define DDIM  256
#define BM 128
#define NBLK 2080            // 64*65/2 upper-triangle 128x128 blocks
#define NCTA 148
#define NTHR 256             // 8 warps: 4(M) x 2(N), warp tile 32x64
#define CHUNK_BYTES 16384    // one [128 rows][128B] swizzled k-chunk
#define TILE_BYTES  65536    // 128 x 256 bf16

__device__ __nv_bfloat16 g_znb[TWO_N * DDIM];
__device__ float g_pr[(size_t)NBLK * 128];  // per-block row partial sums
__device__ float g_pc[(size_t)NBLK * 128];  // per-block col partial sums
__device__ float g_bs[64];                  // per-rowblock loss partial
__device__ int   g_cnt;                     // last-block counter

#define L2E2 2.8853900817779268f    /* 2/ln2 : exp(2d) = 2^(d*L2E2) */

// ---------------------------------------------------------------- helpers --
__device__ __forceinline__ uint32_t smem_u32(const void* p) {
    uint32_t a;
    asm("{ .reg .u64 t; cvta.to.shared.u64 t, %1; cvt.u32.u64 %0, t; }"
        : "=r"(a) : "l"(p));
    return a;
}
__device__ __forceinline__ float ex2f(float x) {
    float y; asm("ex2.approx.f32 %0, %1;" : "=f"(y) : "f"(x)); return y;
}
#define CP_ASYNC16(sm, gp) \
    asm volatile("cp.async.cg.shared.global [%0], [%1], 16;" \
                 :: "r"(sm), "l"(gp) : "memory")
#define CP_COMMIT()  asm volatile("cp.async.commit_group;" ::: "memory")
#define CP_WAIT(n)   asm volatile("cp.async.wait_group %0;" :: "n"(n) : "memory")

__device__ __forceinline__ void ldsm_x4(uint32_t* r, uint32_t addr) {
    asm volatile("ldmatrix.sync.aligned.m8n8.x4.shared.b16 {%0,%1,%2,%3}, [%4];"
                 : "=r"(r[0]), "=r"(r[1]), "=r"(r[2]), "=r"(r[3]) : "r"(addr));
}
__device__ __forceinline__ void mma16816(float* c, const uint32_t* a,
                                         uint32_t b0, uint32_t b1) {
    asm volatile(
        "mma.sync.aligned.m16n8k16.row.col.f32.bf16.bf16.f32 "
        "{%0,%1,%2,%3}, {%4,%5,%6,%7}, {%8,%9}, {%0,%1,%2,%3};"
        : "+f"(c[0]), "+f"(c[1]), "+f"(c[2]), "+f"(c[3])
        : "r"(a[0]), "r"(a[1]), "r"(a[2]), "r"(a[3]), "r"(b0), "r"(b1));
}

// upper-triangle block id in paired-strip order
__device__ __forceinline__ int bidx(int I, int J) {   // I <= J
    return (I < 32) ? (64 * I + J) : (65 * (63 - I) + I + 1 + (J - I));
}
__device__ __forceinline__ void bdecode(int g, int& I, int& J) {
    int p = g / 65, r = g - p * 65;
    if (r < 64 - p) { I = p;      J = p + r; }
    else            { I = 63 - p; J = I + (r - (64 - p)); }
}

// ---------------------------------------------------------------------------
// Kernel 1: L2-normalize rows -> bf16. 2 rows per warp, batched loads.
// ---------------------------------------------------------------------------
__global__ void norm_kernel(const float* __restrict__ z1,
                            const float* __restrict__ z2) {
    int wid = threadIdx.x >> 5, lane = threadIdx.x & 31;
    int row0 = (blockIdx.x * 8 + wid) * 2;
    int row1 = row0 + 1;
    const float4* s0 = reinterpret_cast<const float4*>(
        (row0 < NHALF) ? (z1 + (size_t)row0 * DDIM)
                       : (z2 + (size_t)(row0 - NHALF) * DDIM));
    const float4* s1 = reinterpret_cast<const float4*>(
        (row1 < NHALF) ? (z1 + (size_t)row1 * DDIM)
                       : (z2 + (size_t)(row1 - NHALF) * DDIM));
    // all 4 loads issued before any reduction
    float4 a0 = s0[lane], a1 = s0[lane + 32];
    float4 b0 = s1[lane], b1 = s1[lane + 32];
    float sa = a0.x * a0.x + a0.y * a0.y + a0.z * a0.z + a0.w * a0.w
             + a1.x * a1.x + a1.y * a1.y + a1.z * a1.z + a1.w * a1.w;
    float sb = b0.x * b0.x + b0.y * b0.y + b0.z * b0.z + b0.w * b0.w
             + b1.x * b1.x + b1.y * b1.y + b1.z * b1.z + b1.w * b1.w;
#pragma unroll
    for (int o = 16; o; o >>= 1) {
        sa += __shfl_xor_sync(0xffffffffu, sa, o);
        sb += __shfl_xor_sync(0xffffffffu, sb, o);
    }
    float ia = 1.0f / fmaxf(sqrtf(sa), 1e-8f);
    float ib = 1.0f / fmaxf(sqrtf(sb), 1e-8f);
    uint32_t p0, p1, p2, p3, q0, q1, q2, q3;
    asm("cvt.rn.bf16x2.f32 %0, %1, %2;" : "=r"(p0) : "f"(a0.y * ia), "f"(a0.x * ia));
    asm("cvt.rn.bf16x2.f32 %0, %1, %2;" : "=r"(p1) : "f"(a0.w * ia), "f"(a0.z * ia));
    asm("cvt.rn.bf16x2.f32 %0, %1, %2;" : "=r"(p2) : "f"(a1.y * ia), "f"(a1.x * ia));
    asm("cvt.rn.bf16x2.f32 %0, %1, %2;" : "=r"(p3) : "f"(a1.w * ia), "f"(a1.z * ia));
    asm("cvt.rn.bf16x2.f32 %0, %1, %2;" : "=r"(q0) : "f"(b0.y * ib), "f"(b0.x * ib));
    asm("cvt.rn.bf16x2.f32 %0, %1, %2;" : "=r"(q1) : "f"(b0.w * ib), "f"(b0.z * ib));
    asm("cvt.rn.bf16x2.f32 %0, %1, %2;" : "=r"(q2) : "f"(b1.y * ib), "f"(b1.x * ib));
    asm("cvt.rn.bf16x2.f32 %0, %1, %2;" : "=r"(q3) : "f"(b1.w * ib), "f"(b1.z * ib));
    uint2* d0 = reinterpret_cast<uint2*>(g_znb + (size_t)row0 * DDIM);
    uint2* d1 = reinterpret_cast<uint2*>(g_znb + (size_t)row1 * DDIM);
    d0[lane]      = make_uint2(p0, p1);
    d0[lane + 32] = make_uint2(p2, p3);
    d1[lane]      = make_uint2(q0, q1);
    d1[lane + 32] = make_uint2(q2, q3);
}

// ---------------------------------------------------------------------------
// tile loader: 128 rows x 256 bf16 -> swizzled k-chunks via cp.async
// ---------------------------------------------------------------------------
__device__ __forceinline__ void load_tile(uint32_t sdst, int rowblk, int tid) {
    const char* gsrc = (const char*)(g_znb + (size_t)rowblk * BM * DDIM);
#pragma unroll
    for (int i = 0; i < 16; i++) {
        int unit = i * NTHR + tid;           // row*32 + uu
        int row = unit >> 5, uu = unit & 31;
        uint32_t off = (uint32_t)(row * 128 + (uu & 7) * 16);
        off ^= (off >> 3) & 0x70;
        CP_ASYNC16(sdst + (uu >> 3) * CHUNK_BYTES + off, gsrc + unit * 16);
    }
}

// ---------------------------------------------------------------------------
// Kernel 2: symmetric HMMA GEMM over upper-triangle blocks, deferred epilogue,
// no captures (linear terms recomputed exactly in the reduce kernel).
// ---------------------------------------------------------------------------
__global__ void __launch_bounds__(NTHR, 1) sim_kernel() {
    extern __shared__ char smem_raw[];
    char* sbase = (char*)(((uintptr_t)smem_raw + 1023) & ~(uintptr_t)1023);
    uint32_t sAu = smem_u32(sbase);              // A: 64 KB (single)
    uint32_t sBu = sAu + TILE_BYTES;             // B: 2 x 64 KB

    __shared__ float s_rs[2][BM];                // n-half rowsum partials
    __shared__ float s_cs[8][64];                // [mwarp*2+nhalf][col]

    int tid = threadIdx.x;
    int wid = tid >> 5, lane = tid & 31;
    int cta = blockIdx.x;
    int start = cta * 14 + (cta < 8 ? cta : 8);
    int cnt = 14 + (cta < 8 ? 1 : 0);

    int m_base = (wid >> 1) * 32;
    int n_base = (wid & 1) * 64;
    int mwarp = wid >> 1, nhalf = wid & 1;

    // ---- per-lane ldmatrix address pieces ----
    int rA0 = m_base + (lane & 15);
    int rA1 = rA0 + 16;
    uint32_t kaddA = ((lane >> 4) & 1) * 16;
    uint32_t rowA0 = (uint32_t)rA0 * 128, xA0 = (uint32_t)(rA0 & 7) << 4;
    uint32_t rowA1 = (uint32_t)rA1 * 128, xA1 = (uint32_t)(rA1 & 7) << 4;
    int rBb = n_base + (lane & 7) + ((lane & 16) >> 1);
    uint32_t kaddB = ((lane >> 3) & 1) * 16;
    uint32_t rowB[4], xB[4];
#pragma unroll
    for (int gI = 0; gI < 4; gI++) {
        int r = rBb + gI * 16;
        rowB[gI] = (uint32_t)r * 128;
        xB[gI] = (uint32_t)(r & 7) << 4;
    }
    int lrow[4];
#pragma unroll
    for (int s = 0; s < 4; s++)
        lrow[s] = m_base + (s >> 1) * 16 + (lane >> 2) + (s & 1) * 8;

    float accA[2][8][4], accB[2][8][4];
    float rs[4] = {0.f, 0.f, 0.f, 0.f};
    float cs[8][2];
#pragma unroll
    for (int j = 0; j < 8; j++) { cs[j][0] = 0.f; cs[j][1] = 0.f; }
    int curI;

    auto flush_old = [&](int oI, int oJ, int oblk) {
#pragma unroll
        for (int s2 = 0; s2 < 4; s2++) {
            float v = rs[s2];
            v += __shfl_xor_sync(0xffffffffu, v, 1);
            v += __shfl_xor_sync(0xffffffffu, v, 2);
            if ((lane & 3) == 0) s_rs[nhalf][lrow[s2]] = v;
        }
        if (oI != oJ) {
#pragma unroll
            for (int j = 0; j < 8; j++)
#pragma unroll
                for (int cb = 0; cb < 2; cb++) {
                    float v = cs[j][cb];
                    v += __shfl_xor_sync(0xffffffffu, v, 4);
                    v += __shfl_xor_sync(0xffffffffu, v, 8);
                    v += __shfl_xor_sync(0xffffffffu, v, 16);
                    if (lane < 4)
                        s_cs[mwarp * 2 + nhalf][j * 8 + lane * 2 + cb] = v;
                }
        }
        __syncthreads();
        if (tid < BM) {
            size_t boff = (size_t)oblk * 128 + tid;
            g_pr[boff] = s_rs[0][tid] + s_rs[1][tid];
            if (oI != oJ) {
                int nh = tid >> 6, cc = tid & 63;
                g_pc[boff] = s_cs[nh][cc] + s_cs[2 + nh][cc] +
                             s_cs[4 + nh][cc] + s_cs[6 + nh][cc];
            }
        }
#pragma unroll
        for (int s2 = 0; s2 < 4; s2++) rs[s2] = 0.f;
#pragma unroll
        for (int j = 0; j < 8; j++) { cs[j][0] = 0.f; cs[j][1] = 0.f; }
    };

    auto run_block = [&](float (&acc)[2][8][4], float (&aold)[2][8][4],
                         int n, int oI, int oJ, bool do_old) {
        if (n + 1 < cnt) {
            int In, Jn; bdecode(start + n + 1, In, Jn);
            load_tile(sBu + ((n + 1) & 1) * TILE_BYTES, Jn, tid);
            CP_COMMIT();
            CP_WAIT(1);
        } else {
            CP_WAIT(0);
        }
        __syncthreads();

#pragma unroll
        for (int i = 0; i < 2; i++)
#pragma unroll
            for (int j = 0; j < 8; j++)
#pragma unroll
                for (int q = 0; q < 4; q++) acc[i][j][q] = 0.f;

        uint32_t bbase = sBu + (n & 1) * TILE_BYTES;

#pragma unroll
        for (int s = 0; s < 16; s++) {           // k = s*16
            uint32_t coff = (uint32_t)(s >> 2) * CHUNK_BYTES;
            uint32_t kbA = (uint32_t)(s & 3) * 32 + kaddA;
            uint32_t kbB = (uint32_t)(s & 3) * 32 + kaddB;
            uint32_t a0[4], a1[4], b[4][4];
            ldsm_x4(a0, sAu + coff + rowA0 + (kbA ^ xA0));
            ldsm_x4(a1, sAu + coff + rowA1 + (kbA ^ xA1));
#pragma unroll
            for (int gI = 0; gI < 4; gI++)
                ldsm_x4(b[gI], bbase + coff + rowB[gI] + (kbB ^ xB[gI]));

            // deferred epilogue chunk: element (ii, jj) of old block
            if (do_old) {
                const int ii = s >> 3, jj = s & 7;
#pragma unroll
                for (int q = 0; q < 4; q++) {
                    float e = ex2f(aold[ii][jj][q] * L2E2);
                    rs[ii * 2 + (q >> 1)] += e;
                    cs[jj][q & 1] += e;
                }
            }

#pragma unroll
            for (int j = 0; j < 8; j++) {
                uint32_t b0 = b[j >> 1][(j & 1) * 2];
                uint32_t b1 = b[j >> 1][(j & 1) * 2 + 1];
                mma16816(acc[0][j], a0, b0, b1);
                mma16816(acc[1][j], a1, b0, b1);
            }
        }
        __syncthreads();   // sA / sB[n&1] no longer read

        if (n + 1 < cnt) {
            int In, Jn; bdecode(start + n + 1, In, Jn);
            if (In != curI) { load_tile(sAu, In, tid); CP_COMMIT(); curI = In; }
        }
        if (do_old) flush_old(oI, oJ, start + n - 1);
    };

    // ---- prologue ----
    int I0, J0; bdecode(start, I0, J0);
    load_tile(sAu, I0, tid); CP_COMMIT();
    load_tile(sBu, J0, tid); CP_COMMIT();
    curI = I0;

    bool useA = true;
    int pI = 0, pJ = 0;
#pragma unroll 1
    for (int n = 0; n < cnt; n++) {
        int I, J; bdecode(start + n, I, J);
        if (useA) run_block(accA, accB, n, pI, pJ, n > 0);
        else      run_block(accB, accA, n, pI, pJ, n > 0);
        useA = !useA; pI = I; pJ = J;
    }

    // ---- final (non-interleaved) epilogue for the last block ----
    {
        __syncthreads();
#pragma unroll
        for (int ii = 0; ii < 2; ii++)
#pragma unroll
            for (int jj = 0; jj < 8; jj++)
#pragma unroll
                for (int q = 0; q < 4; q++) {
                    float d = useA ? accB[ii][jj][q] : accA[ii][jj][q];
                    float e = ex2f(d * L2E2);
                    rs[ii * 2 + (q >> 1)] += e;
                    cs[jj][q & 1] += e;
                }
        flush_old(pI, pJ, start + cnt - 1);
    }
}

// ---------------------------------------------------------------------------
// Kernel 3: per-row combine; exact fp32 self/pos dots; last block -> mean.
// ---------------------------------------------------------------------------
__global__ void reduce_kernel(float* __restrict__ out) {
    int R = blockIdx.x, q = threadIdx.x;     // 64 blocks x 128 threads
    int r = R * 128 + q;
    int p = r ^ NHALF;                       // positive-pair row

    // exact fp32 self & pair dots from the bf16 rows (8 bf16 per uint4)
    const uint4* va = reinterpret_cast<const uint4*>(g_znb + (size_t)r * DDIM);
    const uint4* vb = reinterpret_cast<const uint4*>(g_znb + (size_t)p * DDIM);
    float dd = 0.f, pd = 0.f;
#pragma unroll 8
    for (int i = 0; i < DDIM / 8; i++) {
        uint4 wa = va[i], wb = vb[i];
        const uint32_t ua[4] = {wa.x, wa.y, wa.z, wa.w};
        const uint32_t ub[4] = {wb.x, wb.y, wb.z, wb.w};
#pragma unroll
        for (int k = 0; k < 4; k++) {
            float2 fa = __bfloat1622float2(
                *reinterpret_cast<const __nv_bfloat162*>(&ua[k]));
            float2 fb = __bfloat1622float2(
                *reinterpret_cast<const __nv_bfloat162*>(&ub[k]));
            dd += fa.x * fa.x + fa.y * fa.y;
            pd += fa.x * fb.x + fa.y * fb.y;
        }
    }

    // 4 independent partial accumulators over the 64 per-block partials
    float t0 = 0.f, t1 = 0.f, t2 = 0.f, t3 = 0.f;
    {
        int nJ = 64 - R;                     // row-partial count
#pragma unroll 4
        for (int k = 0; k < nJ; k++) {
            float v = g_pr[(size_t)bidx(R, R + k) * 128 + q];
            if ((k & 3) == 0) t0 += v; else if ((k & 3) == 1) t1 += v;
            else if ((k & 3) == 2) t2 += v; else t3 += v;
        }
#pragma unroll 4
        for (int k = 0; k < R; k++) {
            float v = g_pc[(size_t)bidx(k, R) * 128 + q];
            if ((k & 3) == 0) t0 += v; else if ((k & 3) == 1) t1 += v;
            else if ((k & 3) == 2) t2 += v; else t3 += v;
        }
    }
    float tot = (t0 + t1) + (t2 + t3);
    tot -= ex2f(dd * L2E2);                  // remove self term
    float lv = logf(tot) - 2.0f * pd;

    int lane = q & 31;
#pragma unroll
    for (int o = 16; o; o >>= 1) lv += __shfl_xor_sync(0xffffffffu, lv, o);
    __shared__ float w[4];
    __shared__ int slast;
    __shared__ float aa[2];
    if (lane == 0) w[q >> 5] = lv;
    __syncthreads();
    if (q == 0) {
        g_bs[R] = w[0] + w[1] + w[2] + w[3];
        __threadfence();
        slast = (atomicAdd(&g_cnt, 1) == 63);
    }
    __syncthreads();
    if (slast) {
        __threadfence();
        if (q < 64) {
            float v = g_bs[q];
#pragma unroll
            for (int o = 16; o; o >>= 1) v += __shfl_xor_sync(0xffffffffu, v, o);
            if ((q & 31) == 0) aa[q >> 5] = v;
        }
        __syncthreads();
        if (q == 0) {
            out[0] = (aa[0] + aa[1]) / (float)TWO_N;
            g_cnt = 0;                       // reset for graph replay
        }
    }
}

// ---------------------------------------------------------------------------
extern "C" void kernel_launch(void* const* d_in, const int* in_sizes, int n_in,
                              void* d_out, int out_size) {
    const float* z1 = (const float*)d_in[0];
    const float* z2 = (const float*)d_in[1];
    float* out = (float*)d_out;

    norm_kernel<<<TWO_N / 16, 256>>>(z1, z2);

    size_t smem = 3 * TILE_BYTES + 1024;   // 197,632 B
    cudaFuncSetAttribute(sim_kernel, cudaFuncAttributeMaxDynamicSharedMemorySize,
                         (int)smem);
    sim_kernel<<<NCTA, NTHR, smem>>>();

    reduce_kernel<<<64, 128>>>(out);
}

// round 10
// speedup vs baseline: 2.2702x; 1.0292x over previous
#include <cuda_runtime.h>
#include <cuda_bf16.h>
#include <cstdint>

#define TWO_N 8192
#define NHALF 4096
#define DDIM  256
#define BM 128
#define NBLK 2080            // 64*65/2 upper-triangle 128x128 blocks
#define NCTA 148
#define NTHR 256             // 8 warps: 4(M) x 2(N), warp tile 32x64
#define CHUNK_BYTES 16384    // one [128 rows][128B] swizzled k-chunk
#define TILE_BYTES  65536    // 128 x 256 bf16

__device__ __nv_bfloat16 g_znb[TWO_N * DDIM];
__device__ float g_pr[(size_t)NBLK * 128];  // per-block row partial sums
__device__ float g_pc[(size_t)NBLK * 128];  // per-block col partial sums
__device__ float g_cdd[TWO_N];              // self dot per row
__device__ float g_cdp[TWO_N];              // positive-pair dot per row
__device__ float g_bs[64];                  // per-rowblock loss partial
__device__ int   g_cnt;                     // last-block counter

#define L2E2 2.8853900817779268f    /* 2/ln2 : exp(2d) = 2^(d*L2E2) */

// ---------------------------------------------------------------- helpers --
__device__ __forceinline__ uint32_t smem_u32(const void* p) {
    uint32_t a;
    asm("{ .reg .u64 t; cvta.to.shared.u64 t, %1; cvt.u32.u64 %0, t; }"
        : "=r"(a) : "l"(p));
    return a;
}
__device__ __forceinline__ float ex2f(float x) {
    float y; asm("ex2.approx.f32 %0, %1;" : "=f"(y) : "f"(x)); return y;
}
#define CP_ASYNC16(sm, gp) \
    asm volatile("cp.async.cg.shared.global [%0], [%1], 16;" \
                 :: "r"(sm), "l"(gp) : "memory")
#define CP_COMMIT()  asm volatile("cp.async.commit_group;" ::: "memory")
#define CP_WAIT(n)   asm volatile("cp.async.wait_group %0;" :: "n"(n) : "memory")

__device__ __forceinline__ void ldsm_x4(uint32_t* r, uint32_t addr) {
    asm volatile("ldmatrix.sync.aligned.m8n8.x4.shared.b16 {%0,%1,%2,%3}, [%4];"
                 : "=r"(r[0]), "=r"(r[1]), "=r"(r[2]), "=r"(r[3]) : "r"(addr));
}
__device__ __forceinline__ void mma16816(float* c, const uint32_t* a,
                                         uint32_t b0, uint32_t b1) {
    asm volatile(
        "mma.sync.aligned.m16n8k16.row.col.f32.bf16.bf16.f32 "
        "{%0,%1,%2,%3}, {%4,%5,%6,%7}, {%8,%9}, {%0,%1,%2,%3};"
        : "+f"(c[0]), "+f"(c[1]), "+f"(c[2]), "+f"(c[3])
        : "r"(a[0]), "r"(a[1]), "r"(a[2]), "r"(a[3]), "r"(b0), "r"(b1));
}

// upper-triangle block id in paired-strip order
__device__ __forceinline__ int bidx(int I, int J) {   // I <= J
    return (I < 32) ? (64 * I + J) : (65 * (63 - I) + I + 1 + (J - I));
}
__device__ __forceinline__ void bdecode(int g, int& I, int& J) {
    int p = g / 65, r = g - p * 65;
    if (r < 64 - p) { I = p;      J = p + r; }
    else            { I = 63 - p; J = I + (r - (64 - p)); }
}

// ---------------------------------------------------------------------------
// Kernel 1: L2-normalize rows -> bf16. 4 rows per warp, all loads batched.
// ---------------------------------------------------------------------------
__global__ void norm_kernel(const float* __restrict__ z1,
                            const float* __restrict__ z2) {
    int wid = threadIdx.x >> 5, lane = threadIdx.x & 31;
    int rb = (blockIdx.x * 8 + wid) * 4;
    float4 v[4][2];
    float ss[4];
#pragma unroll
    for (int r = 0; r < 4; r++) {
        int row = rb + r;
        const float4* s = reinterpret_cast<const float4*>(
            (row < NHALF) ? (z1 + (size_t)row * DDIM)
                          : (z2 + (size_t)(row - NHALF) * DDIM));
        v[r][0] = s[lane];
        v[r][1] = s[lane + 32];
    }
#pragma unroll
    for (int r = 0; r < 4; r++) {
        float4 a = v[r][0], b = v[r][1];
        ss[r] = a.x * a.x + a.y * a.y + a.z * a.z + a.w * a.w
              + b.x * b.x + b.y * b.y + b.z * b.z + b.w * b.w;
    }
#pragma unroll
    for (int o = 16; o; o >>= 1) {
#pragma unroll
        for (int r = 0; r < 4; r++)
            ss[r] += __shfl_xor_sync(0xffffffffu, ss[r], o);
    }
#pragma unroll
    for (int r = 0; r < 4; r++) {
        float inv = 1.0f / fmaxf(sqrtf(ss[r]), 1e-8f);
        float4 a = v[r][0], b = v[r][1];
        uint32_t p0, p1, p2, p3;
        asm("cvt.rn.bf16x2.f32 %0, %1, %2;" : "=r"(p0) : "f"(a.y * inv), "f"(a.x * inv));
        asm("cvt.rn.bf16x2.f32 %0, %1, %2;" : "=r"(p1) : "f"(a.w * inv), "f"(a.z * inv));
        asm("cvt.rn.bf16x2.f32 %0, %1, %2;" : "=r"(p2) : "f"(b.y * inv), "f"(b.x * inv));
        asm("cvt.rn.bf16x2.f32 %0, %1, %2;" : "=r"(p3) : "f"(b.w * inv), "f"(b.z * inv));
        uint2* d = reinterpret_cast<uint2*>(g_znb + (size_t)(rb + r) * DDIM);
        d[lane]      = make_uint2(p0, p1);
        d[lane + 32] = make_uint2(p2, p3);
    }
}

// ---------------------------------------------------------------------------
// tile loader: 128 rows x 256 bf16 -> swizzled k-chunks via cp.async
// ---------------------------------------------------------------------------
__device__ __forceinline__ void load_tile(uint32_t sdst, int rowblk, int tid) {
    const char* gsrc = (const char*)(g_znb + (size_t)rowblk * BM * DDIM);
#pragma unroll
    for (int i = 0; i < 16; i++) {
        int unit = i * NTHR + tid;           // row*32 + uu
        int row = unit >> 5, uu = unit & 31;
        uint32_t off = (uint32_t)(row * 128 + (uu & 7) * 16);
        off ^= (off >> 3) & 0x70;
        CP_ASYNC16(sdst + (uu >> 3) * CHUNK_BYTES + off, gsrc + unit * 16);
    }
}

// ---------------------------------------------------------------------------
// Kernel 2: symmetric HMMA GEMM over upper-triangle blocks, deferred epilogue.
// grid = 148 persistent CTAs over 2080 blocks in paired-strip order.
// ---------------------------------------------------------------------------
__global__ void __launch_bounds__(NTHR, 1) sim_kernel() {
    extern __shared__ char smem_raw[];
    char* sbase = (char*)(((uintptr_t)smem_raw + 1023) & ~(uintptr_t)1023);
    uint32_t sAu = smem_u32(sbase);              // A: 64 KB (single)
    uint32_t sBu = sAu + TILE_BYTES;             // B: 2 x 64 KB

    __shared__ float s_rs[2][BM];                // n-half rowsum partials
    __shared__ float s_cs[8][64];                // [mwarp*2+nhalf][col]

    int tid = threadIdx.x;
    int wid = tid >> 5, lane = tid & 31;
    int cta = blockIdx.x;
    int start = cta * 14 + (cta < 8 ? cta : 8);
    int cnt = 14 + (cta < 8 ? 1 : 0);

    int m_base = (wid >> 1) * 32;
    int n_base = (wid & 1) * 64;
    int mwarp = wid >> 1, nhalf = wid & 1;

    // ---- per-lane ldmatrix address pieces ----
    int rA0 = m_base + (lane & 15);
    int rA1 = rA0 + 16;
    uint32_t kaddA = ((lane >> 4) & 1) * 16;
    uint32_t rowA0 = (uint32_t)rA0 * 128, xA0 = (uint32_t)(rA0 & 7) << 4;
    uint32_t rowA1 = (uint32_t)rA1 * 128, xA1 = (uint32_t)(rA1 & 7) << 4;
    int rBb = n_base + (lane & 7) + ((lane & 16) >> 1);
    uint32_t kaddB = ((lane >> 3) & 1) * 16;
    uint32_t rowB[4], xB[4];
#pragma unroll
    for (int gI = 0; gI < 4; gI++) {
        int r = rBb + gI * 16;
        rowB[gI] = (uint32_t)r * 128;
        xB[gI] = (uint32_t)(r & 7) << 4;
    }
    int lrow[4];
#pragma unroll
    for (int s = 0; s < 4; s++)
        lrow[s] = m_base + (s >> 1) * 16 + (lane >> 2) + (s & 1) * 8;
    int lcb = n_base + (lane & 3) * 2;           // base local col of this lane

    float accA[2][8][4], accB[2][8][4];
    float rs[4] = {0.f, 0.f, 0.f, 0.f};
    float cs[8][2];
#pragma unroll
    for (int j = 0; j < 8; j++) { cs[j][0] = 0.f; cs[j][1] = 0.f; }
    int curI;

    auto flush_old = [&](int oI, int oJ, int oblk) {
#pragma unroll
        for (int s2 = 0; s2 < 4; s2++) {
            float v = rs[s2];
            v += __shfl_xor_sync(0xffffffffu, v, 1);
            v += __shfl_xor_sync(0xffffffffu, v, 2);
            if ((lane & 3) == 0) s_rs[nhalf][lrow[s2]] = v;
        }
        if (oI != oJ) {
#pragma unroll
            for (int j = 0; j < 8; j++)
#pragma unroll
                for (int cb = 0; cb < 2; cb++) {
                    float v = cs[j][cb];
                    v += __shfl_xor_sync(0xffffffffu, v, 4);
                    v += __shfl_xor_sync(0xffffffffu, v, 8);
                    v += __shfl_xor_sync(0xffffffffu, v, 16);
                    if (lane < 4)
                        s_cs[mwarp * 2 + nhalf][j * 8 + lane * 2 + cb] = v;
                }
        }
        __syncthreads();
        if (tid < BM) {
            size_t boff = (size_t)oblk * 128 + tid;
            g_pr[boff] = s_rs[0][tid] + s_rs[1][tid];
            if (oI != oJ) {
                int nh = tid >> 6, cc = tid & 63;
                g_pc[boff] = s_cs[nh][cc] + s_cs[2 + nh][cc] +
                             s_cs[4 + nh][cc] + s_cs[6 + nh][cc];
            }
        }
#pragma unroll
        for (int s2 = 0; s2 < 4; s2++) rs[s2] = 0.f;
#pragma unroll
        for (int j = 0; j < 8; j++) { cs[j][0] = 0.f; cs[j][1] = 0.f; }
    };

    auto run_block = [&](float (&acc)[2][8][4], float (&aold)[2][8][4],
                         int n, int oI, int oJ, bool do_old) {
        if (n + 1 < cnt) {
            int In, Jn; bdecode(start + n + 1, In, Jn);
            load_tile(sBu + ((n + 1) & 1) * TILE_BYTES, Jn, tid);
            CP_COMMIT();
            CP_WAIT(1);
        } else {
            CP_WAIT(0);
        }
        __syncthreads();

#pragma unroll
        for (int i = 0; i < 2; i++)
#pragma unroll
            for (int j = 0; j < 8; j++)
#pragma unroll
                for (int q = 0; q < 4; q++) acc[i][j][q] = 0.f;

        uint32_t bbase = sBu + (n & 1) * TILE_BYTES;
        bool isdiag = (oI == oJ);
        bool capb = do_old && (isdiag || oJ == oI + 32);

#pragma unroll
        for (int s = 0; s < 16; s++) {           // k = s*16
            uint32_t coff = (uint32_t)(s >> 2) * CHUNK_BYTES;
            uint32_t kbA = (uint32_t)(s & 3) * 32 + kaddA;
            uint32_t kbB = (uint32_t)(s & 3) * 32 + kaddB;
            uint32_t a0[4], a1[4], b[4][4];
            ldsm_x4(a0, sAu + coff + rowA0 + (kbA ^ xA0));
            ldsm_x4(a1, sAu + coff + rowA1 + (kbA ^ xA1));
#pragma unroll
            for (int gI = 0; gI < 4; gI++)
                ldsm_x4(b[gI], bbase + coff + rowB[gI] + (kbB ^ xB[gI]));

            // deferred epilogue chunk: element (ii, jj) of old block
            if (do_old) {
                const int ii = s >> 3, jj = s & 7;
#pragma unroll
                for (int q = 0; q < 4; q++) {
                    float d = aold[ii][jj][q];
                    float e = ex2f(d * L2E2);
                    rs[ii * 2 + (q >> 1)] += e;
                    cs[jj][q & 1] += e;
                    if (capb) {
                        int slot = ii * 2 + (q >> 1);
                        int lc = lcb + jj * 8 + (q & 1);
                        if (lc == lrow[slot]) {
                            int rg = oI * BM + lrow[slot];
                            if (isdiag) g_cdd[rg] = d;
                            else { g_cdp[rg] = d;
                                   g_cdp[oJ * BM + lrow[slot]] = d; }
                        }
                    }
                }
            }

#pragma unroll
            for (int j = 0; j < 8; j++) {
                uint32_t b0 = b[j >> 1][(j & 1) * 2];
                uint32_t b1 = b[j >> 1][(j & 1) * 2 + 1];
                mma16816(acc[0][j], a0, b0, b1);
                mma16816(acc[1][j], a1, b0, b1);
            }
        }
        __syncthreads();   // sA / sB[n&1] no longer read

        if (n + 1 < cnt) {
            int In, Jn; bdecode(start + n + 1, In, Jn);
            if (In != curI) { load_tile(sAu, In, tid); CP_COMMIT(); curI = In; }
        }
        if (do_old) flush_old(oI, oJ, start + n - 1);
    };

    // ---- prologue ----
    int I0, J0; bdecode(start, I0, J0);
    load_tile(sAu, I0, tid); CP_COMMIT();
    load_tile(sBu, J0, tid); CP_COMMIT();
    curI = I0;

    bool useA = true;
    int pI = 0, pJ = 0;
#pragma unroll 1
    for (int n = 0; n < cnt; n++) {
        int I, J; bdecode(start + n, I, J);
        if (useA) run_block(accA, accB, n, pI, pJ, n > 0);
        else      run_block(accB, accA, n, pI, pJ, n > 0);
        useA = !useA; pI = I; pJ = J;
    }

    // ---- final (non-interleaved) epilogue for the last block ----
    {
        __syncthreads();
        bool isdiag = (pI == pJ);
        bool capb = isdiag || (pJ == pI + 32);
#pragma unroll
        for (int ii = 0; ii < 2; ii++)
#pragma unroll
            for (int jj = 0; jj < 8; jj++)
#pragma unroll
                for (int q = 0; q < 4; q++) {
                    float d = useA ? accB[ii][jj][q] : accA[ii][jj][q];
                    float e = ex2f(d * L2E2);
                    rs[ii * 2 + (q >> 1)] += e;
                    cs[jj][q & 1] += e;
                    if (capb) {
                        int slot = ii * 2 + (q >> 1);
                        int lc = lcb + jj * 8 + (q & 1);
                        if (lc == lrow[slot]) {
                            int rg = pI * BM + lrow[slot];
                            if (isdiag) g_cdd[rg] = d;
                            else { g_cdp[rg] = d;
                                   g_cdp[pJ * BM + lrow[slot]] = d; }
                        }
                    }
                }
        flush_old(pI, pJ, start + cnt - 1);
    }
}

// ---------------------------------------------------------------------------
// Kernel 3: per-row combine of partials -> loss; last block does final mean.
// ---------------------------------------------------------------------------
__global__ void reduce_kernel(float* __restrict__ out) {
    int R = blockIdx.x, q = threadIdx.x;     // 64 blocks x 128 threads
    int r = R * 128 + q;
    float tot = 0.f;
#pragma unroll 4
    for (int J = R; J < 64; J++) tot += g_pr[(size_t)bidx(R, J) * 128 + q];
#pragma unroll 4
    for (int I = 0; I < R; I++)  tot += g_pc[(size_t)bidx(I, R) * 128 + q];
    tot -= ex2f(g_cdd[r] * L2E2);            // remove self term bit-exactly
    float lv = logf(tot) - 2.0f * g_cdp[r];

    int lane = q & 31;
#pragma unroll
    for (int o = 16; o; o >>= 1) lv += __shfl_xor_sync(0xffffffffu, lv, o);
    __shared__ float w[4];
    __shared__ int slast;
    __shared__ float aa[2];
    if (lane == 0) w[q >> 5] = lv;
    __syncthreads();
    if (q == 0) {
        g_bs[R] = w[0] + w[1] + w[2] + w[3];
        __threadfence();
        slast = (atomicAdd(&g_cnt, 1) == 63);
    }
    __syncthreads();
    if (slast) {
        __threadfence();
        if (q < 64) {
            float v = g_bs[q];
#pragma unroll
            for (int o = 16; o; o >>= 1) v += __shfl_xor_sync(0xffffffffu, v, o);
            if ((q & 31) == 0) aa[q >> 5] = v;
        }
        __syncthreads();
        if (q == 0) {
            out[0] = (aa[0] + aa[1]) / (float)TWO_N;
            g_cnt = 0;                       // reset for graph replay
        }
    }
}

// ---------------------------------------------------------------------------
extern "C" void kernel_launch(void* const* d_in, const int* in_sizes, int n_in,
                              void* d_out, int out_size) {
    const float* z1 = (const float*)d_in[0];
    const float* z2 = (const float*)d_in[1];
    float* out = (float*)d_out;

    norm_kernel<<<TWO_N / 32, 256>>>(z1, z2);

    size_t smem = 3 * TILE_BYTES + 1024;   // 197,632 B
    cudaFuncSetAttribute(sim_kernel, cudaFuncAttributeMaxDynamicSharedMemorySize,
                         (int)smem);
    sim_kernel<<<NCTA, NTHR, smem>>>();

    reduce_kernel<<<64, 128>>>(out);
}

// round 11
// speedup vs baseline: 2.3374x; 1.0296x over previous
#include <cuda_runtime.h>
#include <cuda_bf16.h>
#include <cstdint>

#define TWO_N 8192
#define NHALF 4096
#define DDIM  256
#define BM 128
#define NBLK 2080            // 64*65/2 upper-triangle 128x128 blocks
#define NCTA 148
#define NTHR 256             // 8 warps: 4(M) x 2(N), warp tile 32x64
#define CHUNK_BYTES 16384    // one [128 rows][128B] swizzled k-chunk
#define TILE_BYTES  65536    // 128 x 256 bf16

__device__ __nv_bfloat16 g_znb[TWO_N * DDIM];
__device__ float g_pr[(size_t)NBLK * 128];  // per-block row partial sums
__device__ float g_pc[(size_t)NBLK * 128];  // per-block col partial sums
__device__ float g_cdd[TWO_N];              // self dot per row
__device__ float g_cdp[TWO_N];              // positive-pair dot per row
__device__ float g_bs[64];                  // per-rowblock loss partial
__device__ int   g_cnt;                     // last-block counter

#define L2E2 2.8853900817779268f    /* 2/ln2 : exp(2d) = 2^(d*L2E2) */

// ---------------------------------------------------------------- helpers --
__device__ __forceinline__ uint32_t smem_u32(const void* p) {
    uint32_t a;
    asm("{ .reg .u64 t; cvta.to.shared.u64 t, %1; cvt.u32.u64 %0, t; }"
        : "=r"(a) : "l"(p));
    return a;
}
__device__ __forceinline__ float ex2f(float x) {
    float y; asm("ex2.approx.f32 %0, %1;" : "=f"(y) : "f"(x)); return y;
}
#define CP_ASYNC16(sm, gp) \
    asm volatile("cp.async.cg.shared.global [%0], [%1], 16;" \
                 :: "r"(sm), "l"(gp) : "memory")
#define CP_COMMIT()  asm volatile("cp.async.commit_group;" ::: "memory")
#define CP_WAIT(n)   asm volatile("cp.async.wait_group %0;" :: "n"(n) : "memory")

__device__ __forceinline__ void ldsm_x4(uint32_t* r, uint32_t addr) {
    asm volatile("ldmatrix.sync.aligned.m8n8.x4.shared.b16 {%0,%1,%2,%3}, [%4];"
                 : "=r"(r[0]), "=r"(r[1]), "=r"(r[2]), "=r"(r[3]) : "r"(addr));
}
__device__ __forceinline__ void mma16816(float* c, const uint32_t* a,
                                         uint32_t b0, uint32_t b1) {
    asm volatile(
        "mma.sync.aligned.m16n8k16.row.col.f32.bf16.bf16.f32 "
        "{%0,%1,%2,%3}, {%4,%5,%6,%7}, {%8,%9}, {%0,%1,%2,%3};"
        : "+f"(c[0]), "+f"(c[1]), "+f"(c[2]), "+f"(c[3])
        : "r"(a[0]), "r"(a[1]), "r"(a[2]), "r"(a[3]), "r"(b0), "r"(b1));
}

// upper-triangle block id in paired-strip order
__device__ __forceinline__ int bidx(int I, int J) {   // I <= J
    return (I < 32) ? (64 * I + J) : (65 * (63 - I) + I + 1 + (J - I));
}
__device__ __forceinline__ void bdecode(int g, int& I, int& J) {
    int p = g / 65, r = g - p * 65;
    if (r < 64 - p) { I = p;      J = p + r; }
    else            { I = 63 - p; J = I + (r - (64 - p)); }
}

// ---------------------------------------------------------------------------
// Kernel 1: L2-normalize rows -> bf16. 2 rows per warp, batched loads,
// adjacent-chunk layout so each thread emits one STG.128 per row.
// ---------------------------------------------------------------------------
__global__ void norm_kernel(const float* __restrict__ z1,
                            const float* __restrict__ z2) {
    int wid = threadIdx.x >> 5, lane = threadIdx.x & 31;
    int row0 = (blockIdx.x * 8 + wid) * 2;
    int row1 = row0 + 1;
    const float4* s0 = reinterpret_cast<const float4*>(
        (row0 < NHALF) ? (z1 + (size_t)row0 * DDIM)
                       : (z2 + (size_t)(row0 - NHALF) * DDIM));
    const float4* s1 = reinterpret_cast<const float4*>(
        (row1 < NHALF) ? (z1 + (size_t)row1 * DDIM)
                       : (z2 + (size_t)(row1 - NHALF) * DDIM));
    // all 4 loads issued before any reduction; adjacent float4 pairs
    float4 a0 = s0[lane * 2], a1 = s0[lane * 2 + 1];
    float4 b0 = s1[lane * 2], b1 = s1[lane * 2 + 1];
    float sa = a0.x * a0.x + a0.y * a0.y + a0.z * a0.z + a0.w * a0.w
             + a1.x * a1.x + a1.y * a1.y + a1.z * a1.z + a1.w * a1.w;
    float sb = b0.x * b0.x + b0.y * b0.y + b0.z * b0.z + b0.w * b0.w
             + b1.x * b1.x + b1.y * b1.y + b1.z * b1.z + b1.w * b1.w;
#pragma unroll
    for (int o = 16; o; o >>= 1) {
        sa += __shfl_xor_sync(0xffffffffu, sa, o);
        sb += __shfl_xor_sync(0xffffffffu, sb, o);
    }
    float ia = 1.0f / fmaxf(sqrtf(sa), 1e-8f);
    float ib = 1.0f / fmaxf(sqrtf(sb), 1e-8f);
    uint4 pa, pb;
    asm("cvt.rn.bf16x2.f32 %0, %1, %2;" : "=r"(pa.x) : "f"(a0.y * ia), "f"(a0.x * ia));
    asm("cvt.rn.bf16x2.f32 %0, %1, %2;" : "=r"(pa.y) : "f"(a0.w * ia), "f"(a0.z * ia));
    asm("cvt.rn.bf16x2.f32 %0, %1, %2;" : "=r"(pa.z) : "f"(a1.y * ia), "f"(a1.x * ia));
    asm("cvt.rn.bf16x2.f32 %0, %1, %2;" : "=r"(pa.w) : "f"(a1.w * ia), "f"(a1.z * ia));
    asm("cvt.rn.bf16x2.f32 %0, %1, %2;" : "=r"(pb.x) : "f"(b0.y * ib), "f"(b0.x * ib));
    asm("cvt.rn.bf16x2.f32 %0, %1, %2;" : "=r"(pb.y) : "f"(b0.w * ib), "f"(b0.z * ib));
    asm("cvt.rn.bf16x2.f32 %0, %1, %2;" : "=r"(pb.z) : "f"(b1.y * ib), "f"(b1.x * ib));
    asm("cvt.rn.bf16x2.f32 %0, %1, %2;" : "=r"(pb.w) : "f"(b1.w * ib), "f"(b1.z * ib));
    reinterpret_cast<uint4*>(g_znb + (size_t)row0 * DDIM)[lane] = pa;
    reinterpret_cast<uint4*>(g_znb + (size_t)row1 * DDIM)[lane] = pb;
}

// ---------------------------------------------------------------------------
// tile loader: 128 rows x 256 bf16 -> swizzled k-chunks via cp.async
// ---------------------------------------------------------------------------
__device__ __forceinline__ void load_tile(uint32_t sdst, int rowblk, int tid) {
    const char* gsrc = (const char*)(g_znb + (size_t)rowblk * BM * DDIM);
#pragma unroll
    for (int i = 0; i < 16; i++) {
        int unit = i * NTHR + tid;           // row*32 + uu
        int row = unit >> 5, uu = unit & 31;
        uint32_t off = (uint32_t)(row * 128 + (uu & 7) * 16);
        off ^= (off >> 3) & 0x70;
        CP_ASYNC16(sdst + (uu >> 3) * CHUNK_BYTES + off, gsrc + unit * 16);
    }
}

// ---------------------------------------------------------------------------
// Kernel 2: symmetric HMMA GEMM over upper-triangle blocks, deferred epilogue.
// grid = 148 persistent CTAs over 2080 blocks in paired-strip order.
// (byte-identical logic to the R6 champion)
// ---------------------------------------------------------------------------
__global__ void __launch_bounds__(NTHR, 1) sim_kernel() {
    extern __shared__ char smem_raw[];
    char* sbase = (char*)(((uintptr_t)smem_raw + 1023) & ~(uintptr_t)1023);
    uint32_t sAu = smem_u32(sbase);              // A: 64 KB (single)
    uint32_t sBu = sAu + TILE_BYTES;             // B: 2 x 64 KB

    __shared__ float s_rs[2][BM];                // n-half rowsum partials
    __shared__ float s_cs[8][64];                // [mwarp*2+nhalf][col]

    int tid = threadIdx.x;
    int wid = tid >> 5, lane = tid & 31;
    int cta = blockIdx.x;
    int start = cta * 14 + (cta < 8 ? cta : 8);
    int cnt = 14 + (cta < 8 ? 1 : 0);

    int m_base = (wid >> 1) * 32;
    int n_base = (wid & 1) * 64;
    int mwarp = wid >> 1, nhalf = wid & 1;

    // ---- per-lane ldmatrix address pieces ----
    int rA0 = m_base + (lane & 15);
    int rA1 = rA0 + 16;
    uint32_t kaddA = ((lane >> 4) & 1) * 16;
    uint32_t rowA0 = (uint32_t)rA0 * 128, xA0 = (uint32_t)(rA0 & 7) << 4;
    uint32_t rowA1 = (uint32_t)rA1 * 128, xA1 = (uint32_t)(rA1 & 7) << 4;
    int rBb = n_base + (lane & 7) + ((lane & 16) >> 1);
    uint32_t kaddB = ((lane >> 3) & 1) * 16;
    uint32_t rowB[4], xB[4];
#pragma unroll
    for (int gI = 0; gI < 4; gI++) {
        int r = rBb + gI * 16;
        rowB[gI] = (uint32_t)r * 128;
        xB[gI] = (uint32_t)(r & 7) << 4;
    }
    int lrow[4];
#pragma unroll
    for (int s = 0; s < 4; s++)
        lrow[s] = m_base + (s >> 1) * 16 + (lane >> 2) + (s & 1) * 8;
    int lcb = n_base + (lane & 3) * 2;           // base local col of this lane

    float accA[2][8][4], accB[2][8][4];
    float rs[4] = {0.f, 0.f, 0.f, 0.f};
    float cs[8][2];
#pragma unroll
    for (int j = 0; j < 8; j++) { cs[j][0] = 0.f; cs[j][1] = 0.f; }
    int curI;

    auto flush_old = [&](int oI, int oJ, int oblk) {
#pragma unroll
        for (int s2 = 0; s2 < 4; s2++) {
            float v = rs[s2];
            v += __shfl_xor_sync(0xffffffffu, v, 1);
            v += __shfl_xor_sync(0xffffffffu, v, 2);
            if ((lane & 3) == 0) s_rs[nhalf][lrow[s2]] = v;
        }
        if (oI != oJ) {
#pragma unroll
            for (int j = 0; j < 8; j++)
#pragma unroll
                for (int cb = 0; cb < 2; cb++) {
                    float v = cs[j][cb];
                    v += __shfl_xor_sync(0xffffffffu, v, 4);
                    v += __shfl_xor_sync(0xffffffffu, v, 8);
                    v += __shfl_xor_sync(0xffffffffu, v, 16);
                    if (lane < 4)
                        s_cs[mwarp * 2 + nhalf][j * 8 + lane * 2 + cb] = v;
                }
        }
        __syncthreads();
        if (tid < BM) {
            size_t boff = (size_t)oblk * 128 + tid;
            g_pr[boff] = s_rs[0][tid] + s_rs[1][tid];
            if (oI != oJ) {
                int nh = tid >> 6, cc = tid & 63;
                g_pc[boff] = s_cs[nh][cc] + s_cs[2 + nh][cc] +
                             s_cs[4 + nh][cc] + s_cs[6 + nh][cc];
            }
        }
#pragma unroll
        for (int s2 = 0; s2 < 4; s2++) rs[s2] = 0.f;
#pragma unroll
        for (int j = 0; j < 8; j++) { cs[j][0] = 0.f; cs[j][1] = 0.f; }
    };

    auto run_block = [&](float (&acc)[2][8][4], float (&aold)[2][8][4],
                         int n, int oI, int oJ, bool do_old) {
        if (n + 1 < cnt) {
            int In, Jn; bdecode(start + n + 1, In, Jn);
            load_tile(sBu + ((n + 1) & 1) * TILE_BYTES, Jn, tid);
            CP_COMMIT();
            CP_WAIT(1);
        } else {
            CP_WAIT(0);
        }
        __syncthreads();

#pragma unroll
        for (int i = 0; i < 2; i++)
#pragma unroll
            for (int j = 0; j < 8; j++)
#pragma unroll
                for (int q = 0; q < 4; q++) acc[i][j][q] = 0.f;

        uint32_t bbase = sBu + (n & 1) * TILE_BYTES;
        bool isdiag = (oI == oJ);
        bool capb = do_old && (isdiag || oJ == oI + 32);

#pragma unroll
        for (int s = 0; s < 16; s++) {           // k = s*16
            uint32_t coff = (uint32_t)(s >> 2) * CHUNK_BYTES;
            uint32_t kbA = (uint32_t)(s & 3) * 32 + kaddA;
            uint32_t kbB = (uint32_t)(s & 3) * 32 + kaddB;
            uint32_t a0[4], a1[4], b[4][4];
            ldsm_x4(a0, sAu + coff + rowA0 + (kbA ^ xA0));
            ldsm_x4(a1, sAu + coff + rowA1 + (kbA ^ xA1));
#pragma unroll
            for (int gI = 0; gI < 4; gI++)
                ldsm_x4(b[gI], bbase + coff + rowB[gI] + (kbB ^ xB[gI]));

            // deferred epilogue chunk: element (ii, jj) of old block
            if (do_old) {
                const int ii = s >> 3, jj = s & 7;
#pragma unroll
                for (int q = 0; q < 4; q++) {
                    float d = aold[ii][jj][q];
                    float e = ex2f(d * L2E2);
                    rs[ii * 2 + (q >> 1)] += e;
                    cs[jj][q & 1] += e;
                    if (capb) {
                        int slot = ii * 2 + (q >> 1);
                        int lc = lcb + jj * 8 + (q & 1);
                        if (lc == lrow[slot]) {
                            int rg = oI * BM + lrow[slot];
                            if (isdiag) g_cdd[rg] = d;
                            else { g_cdp[rg] = d;
                                   g_cdp[oJ * BM + lrow[slot]] = d; }
                        }
                    }
                }
            }

#pragma unroll
            for (int j = 0; j < 8; j++) {
                uint32_t b0 = b[j >> 1][(j & 1) * 2];
                uint32_t b1 = b[j >> 1][(j & 1) * 2 + 1];
                mma16816(acc[0][j], a0, b0, b1);
                mma16816(acc[1][j], a1, b0, b1);
            }
        }
        __syncthreads();   // sA / sB[n&1] no longer read

        if (n + 1 < cnt) {
            int In, Jn; bdecode(start + n + 1, In, Jn);
            if (In != curI) { load_tile(sAu, In, tid); CP_COMMIT(); curI = In; }
        }
        if (do_old) flush_old(oI, oJ, start + n - 1);
    };

    // ---- prologue ----
    int I0, J0; bdecode(start, I0, J0);
    load_tile(sAu, I0, tid); CP_COMMIT();
    load_tile(sBu, J0, tid); CP_COMMIT();
    curI = I0;

    bool useA = true;
    int pI = 0, pJ = 0;
#pragma unroll 1
    for (int n = 0; n < cnt; n++) {
        int I, J; bdecode(start + n, I, J);
        if (useA) run_block(accA, accB, n, pI, pJ, n > 0);
        else      run_block(accB, accA, n, pI, pJ, n > 0);
        useA = !useA; pI = I; pJ = J;
    }

    // ---- final (non-interleaved) epilogue for the last block ----
    {
        __syncthreads();
        bool isdiag = (pI == pJ);
        bool capb = isdiag || (pJ == pI + 32);
#pragma unroll
        for (int ii = 0; ii < 2; ii++)
#pragma unroll
            for (int jj = 0; jj < 8; jj++)
#pragma unroll
                for (int q = 0; q < 4; q++) {
                    float d = useA ? accB[ii][jj][q] : accA[ii][jj][q];
                    float e = ex2f(d * L2E2);
                    rs[ii * 2 + (q >> 1)] += e;
                    cs[jj][q & 1] += e;
                    if (capb) {
                        int slot = ii * 2 + (q >> 1);
                        int lc = lcb + jj * 8 + (q & 1);
                        if (lc == lrow[slot]) {
                            int rg = pI * BM + lrow[slot];
                            if (isdiag) g_cdd[rg] = d;
                            else { g_cdp[rg] = d;
                                   g_cdp[pJ * BM + lrow[slot]] = d; }
                        }
                    }
                }
        flush_old(pI, pJ, start + cnt - 1);
    }
}

// ---------------------------------------------------------------------------
// Kernel 3: per-row combine of partials -> loss; last block does final mean.
// Higher-MLP partial walk (unroll 8, two interleaved accumulators).
// ---------------------------------------------------------------------------
__global__ void reduce_kernel(float* __restrict__ out) {
    int R = blockIdx.x, q = threadIdx.x;     // 64 blocks x 128 threads
    int r = R * 128 + q;
    float t0 = 0.f, t1 = 0.f;
    {
        int nJ = 64 - R;
#pragma unroll 8
        for (int k = 0; k < nJ; k++) {
            float v = g_pr[(size_t)bidx(R, R + k) * 128 + q];
            if (k & 1) t1 += v; else t0 += v;
        }
#pragma unroll 8
        for (int k = 0; k < R; k++) {
            float v = g_pc[(size_t)bidx(k, R) * 128 + q];
            if (k & 1) t1 += v; else t0 += v;
        }
    }
    float tot = t0 + t1;
    tot -= ex2f(g_cdd[r] * L2E2);            // remove self term bit-exactly
    float lv = logf(tot) - 2.0f * g_cdp[r];

    int lane = q & 31;
#pragma unroll
    for (int o = 16; o; o >>= 1) lv += __shfl_xor_sync(0xffffffffu, lv, o);
    __shared__ float w[4];
    __shared__ int slast;
    __shared__ float aa[2];
    if (lane == 0) w[q >> 5] = lv;
    __syncthreads();
    if (q == 0) {
        g_bs[R] = w[0] + w[1] + w[2] + w[3];
        __threadfence();
        slast = (atomicAdd(&g_cnt, 1) == 63);
    }
    __syncthreads();
    if (slast) {
        __threadfence();
        if (q < 64) {
            float v = g_bs[q];
#pragma unroll
            for (int o = 16; o; o >>= 1) v += __shfl_xor_sync(0xffffffffu, v, o);
            if ((q & 31) == 0) aa[q >> 5] = v;
        }
        __syncthreads();
        if (q == 0) {
            out[0] = (aa[0] + aa[1]) / (float)TWO_N;
            g_cnt = 0;                       // reset for graph replay
        }
    }
}

// ---------------------------------------------------------------------------
extern "C" void kernel_launch(void* const* d_in, const int* in_sizes, int n_in,
                              void* d_out, int out_size) {
    const float* z1 = (const float*)d_in[0];
    const float* z2 = (const float*)d_in[1];
    float* out = (float*)d_out;

    norm_kernel<<<TWO_N / 16, 256>>>(z1, z2);

    size_t smem = 3 * TILE_BYTES + 1024;   // 197,632 B
    cudaFuncSetAttribute(sim_kernel, cudaFuncAttributeMaxDynamicSharedMemorySize,
                         (int)smem);
    sim_kernel<<<NCTA, NTHR, smem>>>();

    reduce_kernel<<<64, 128>>>(out);
}